// round 1
// baseline (speedup 1.0000x reference)
#include <cuda_runtime.h>
#include <math.h>

#define T_CTX 5
#define DIM 32
#define HEADS 4
#define HDIM 8
#define NTHREADS (T_CTX * DIM)   // 160

__global__ __launch_bounds__(NTHREADS, 1)
void fused_block_kernel(const float* __restrict__ X,
                        const float* __restrict__ WQ,
                        const float* __restrict__ WK,
                        const float* __restrict__ WV,
                        const float* __restrict__ Wproj,
                        const float* __restrict__ bproj,
                        const float* __restrict__ W1,
                        const float* __restrict__ b1,
                        const float* __restrict__ W2,
                        const float* __restrict__ b2,
                        float* __restrict__ out)
{
    __shared__ float sX[T_CTX][DIM];
    __shared__ float sQ[T_CTX][DIM];
    __shared__ float sK[T_CTX][DIM];
    __shared__ float sV[T_CTX][DIM];
    __shared__ float sA[HEADS][T_CTX][T_CTX];
    __shared__ float sY[T_CTX][DIM];    // Ycat: [t][h*8+d]
    __shared__ float sYp[T_CTX][DIM];   // Yproj
    __shared__ float sH1[T_CTX][DIM];

    const int tid = threadIdx.x;        // 0..159
    const int r = tid >> 5;             // token row 0..4
    const int c = tid & 31;             // feature col 0..31

    // stage 0: load X
    sX[r][c] = X[tid];
    __syncthreads();

    // stage 1: Q/K/V projections  (x @ W.T  ->  out[r][c] = sum_j X[r][j] * W[c][j])
    {
        float q = 0.f, k = 0.f, v = 0.f;
        const float* wq = WQ + c * DIM;
        const float* wk = WK + c * DIM;
        const float* wv = WV + c * DIM;
        #pragma unroll
        for (int j = 0; j < DIM; ++j) {
            const float x = sX[r][j];
            q = fmaf(x, wq[j], q);
            k = fmaf(x, wk[j], k);
            v = fmaf(x, wv[j], v);
        }
        sQ[r][c] = q; sK[r][c] = k; sV[r][c] = v;
    }
    __syncthreads();

    // stage 2: attention scores A[h][q][k] with causal mask, scale 1/sqrt(DIM)
    if (tid < HEADS * T_CTX * T_CTX) {   // 100 threads
        const int h  = tid / (T_CTX * T_CTX);
        const int rem = tid % (T_CTX * T_CTX);
        const int qi = rem / T_CTX;
        const int ki = rem % T_CTX;
        float a;
        if (ki <= qi) {
            a = 0.f;
            #pragma unroll
            for (int d = 0; d < HDIM; ++d)
                a = fmaf(sQ[qi][h * HDIM + d], sK[ki][h * HDIM + d], a);
            a *= 0.1767766952966368811f;   // 1/sqrt(32)
        } else {
            a = -INFINITY;
        }
        sA[h][qi][ki] = a;
    }
    __syncthreads();

    // stage 3: softmax over last dim, per (h, qi) row — 20 rows
    if (tid < HEADS * T_CTX) {
        const int h  = tid / T_CTX;
        const int qi = tid % T_CTX;
        float m = -INFINITY;
        #pragma unroll
        for (int ki = 0; ki < T_CTX; ++ki) m = fmaxf(m, sA[h][qi][ki]);
        float e[T_CTX];
        float s = 0.f;
        #pragma unroll
        for (int ki = 0; ki < T_CTX; ++ki) {
            // masked entries: exp(-inf - m) = 0
            e[ki] = expf(sA[h][qi][ki] - m);
            s += e[ki];
        }
        const float inv = 1.f / s;
        #pragma unroll
        for (int ki = 0; ki < T_CTX; ++ki) sA[h][qi][ki] = e[ki] * inv;
    }
    __syncthreads();

    // stage 4: Y = S @ V per head; write directly in concat layout [t][h*8+d]
    {
        const int h = c >> 3;   // c = h*8 + d
        float y = 0.f;
        #pragma unroll
        for (int ki = 0; ki < T_CTX; ++ki)
            y = fmaf(sA[h][r][ki], sV[ki][c], y);
        sY[r][c] = y;
    }
    __syncthreads();

    // stage 5: Yproj = Ycat @ Wproj.T + bproj
    {
        float yp = bproj[c];
        const float* wp = Wproj + c * DIM;
        #pragma unroll
        for (int j = 0; j < DIM; ++j)
            yp = fmaf(sY[r][j], wp[j], yp);
        sYp[r][c] = yp;
    }
    __syncthreads();

    // stage 6: H1 = relu(Yproj @ W1.T + b1)
    {
        float h1 = b1[c];
        const float* w1 = W1 + c * DIM;
        #pragma unroll
        for (int j = 0; j < DIM; ++j)
            h1 = fmaf(sYp[r][j], w1[j], h1);
        sH1[r][c] = fmaxf(h1, 0.f);
    }
    __syncthreads();

    // stage 7: Y2 = H1 @ W2.T + b2 ; out = Y2 + Yproj
    {
        float y2 = b2[c];
        const float* w2 = W2 + c * DIM;
        #pragma unroll
        for (int j = 0; j < DIM; ++j)
            y2 = fmaf(sH1[r][j], w2[j], y2);
        out[tid] = y2 + sYp[r][c];
    }
}

extern "C" void kernel_launch(void* const* d_in, const int* in_sizes, int n_in,
                              void* d_out, int out_size)
{
    const float* X     = (const float*)d_in[0];
    const float* WQ    = (const float*)d_in[1];
    const float* WK    = (const float*)d_in[2];
    const float* WV    = (const float*)d_in[3];
    const float* Wproj = (const float*)d_in[4];
    const float* bproj = (const float*)d_in[5];
    const float* W1    = (const float*)d_in[6];
    const float* b1    = (const float*)d_in[7];
    const float* W2    = (const float*)d_in[8];
    const float* b2    = (const float*)d_in[9];
    float* out = (float*)d_out;

    fused_block_kernel<<<1, NTHREADS>>>(X, WQ, WK, WV, Wproj, bproj,
                                        W1, b1, W2, b2, out);
}

// round 2
// speedup vs baseline: 3.1490x; 3.1490x over previous
#include <cuda_runtime.h>
#include <math.h>

#define T_CTX 5
#define DIM 32
#define HEADS 4
#define HDIM 8
#define NTHREADS (T_CTX * DIM)   // 160
#define WPAD 33                  // padded row stride (floats) -> conflict-free

__global__ __launch_bounds__(NTHREADS, 1)
void fused_block_kernel(const float* __restrict__ X,
                        const float* __restrict__ WQ,
                        const float* __restrict__ WK,
                        const float* __restrict__ WV,
                        const float* __restrict__ Wproj,
                        const float* __restrict__ bproj,
                        const float* __restrict__ W1,
                        const float* __restrict__ b1,
                        const float* __restrict__ W2,
                        const float* __restrict__ b2,
                        float* __restrict__ out)
{
    // 0:WQ 1:WK 2:WV 3:Wproj 4:W1 5:W2
    __shared__ float sW[6][DIM][WPAD];
    __shared__ float sB[3][DIM];        // bproj, b1, b2
    __shared__ float sX[T_CTX][DIM];
    __shared__ float sQ[T_CTX][DIM];
    __shared__ float sK[T_CTX][DIM];
    __shared__ float sV[T_CTX][DIM];
    __shared__ float sS[HEADS][T_CTX][T_CTX];  // softmax probs
    __shared__ float sY[T_CTX][DIM];    // Ycat
    __shared__ float sYp[T_CTX][DIM];   // Yproj
    __shared__ float sH1[T_CTX][DIM];

    const int tid = threadIdx.x;        // 0..159
    const int r = tid >> 5;             // token row 0..4
    const int c = tid & 31;             // feature col 0..31

    // ---- prefetch: all weights via independent float4 LDGs (max MLP) ----
    #define PREFETCH_W(m, gptr)                                              \
        _Pragma("unroll")                                                    \
        for (int i = tid; i < 256; i += NTHREADS) {                          \
            float4 v = ((const float4*)(gptr))[i];                           \
            int row = i >> 3;                                                \
            int c4  = (i & 7) << 2;                                          \
            sW[m][row][c4 + 0] = v.x;                                        \
            sW[m][row][c4 + 1] = v.y;                                        \
            sW[m][row][c4 + 2] = v.z;                                        \
            sW[m][row][c4 + 3] = v.w;                                        \
        }
    PREFETCH_W(0, WQ)
    PREFETCH_W(1, WK)
    PREFETCH_W(2, WV)
    PREFETCH_W(3, Wproj)
    PREFETCH_W(4, W1)
    PREFETCH_W(5, W2)

    if (tid < 3 * DIM) {
        const int which = tid >> 5;     // 0,1,2
        const float* b = (which == 0) ? bproj : (which == 1) ? b1 : b2;
        sB[which][c] = b[c];
    }
    sX[r][c] = X[tid];
    __syncthreads();

    // ---- stage 1: Q/K/V projections (x @ W.T) ----
    {
        float q = 0.f, k = 0.f, v = 0.f;
        #pragma unroll
        for (int j = 0; j < DIM; ++j) {
            const float x = sX[r][j];
            q = fmaf(x, sW[0][c][j], q);
            k = fmaf(x, sW[1][c][j], k);
            v = fmaf(x, sW[2][c][j], v);
        }
        sQ[r][c] = q; sK[r][c] = k; sV[r][c] = v;
    }
    __syncthreads();

    // ---- stage 2: scores + causal mask + softmax, one thread per (h,q) row ----
    if (tid < HEADS * T_CTX) {   // 20 threads
        const int h  = tid / T_CTX;
        const int qi = tid % T_CTX;
        float a[T_CTX];
        float m = -INFINITY;
        #pragma unroll
        for (int ki = 0; ki < T_CTX; ++ki) {
            if (ki <= qi) {
                float s = 0.f;
                #pragma unroll
                for (int d = 0; d < HDIM; ++d)
                    s = fmaf(sQ[qi][h * HDIM + d], sK[ki][h * HDIM + d], s);
                a[ki] = s * 0.1767766952966368811f;   // 1/sqrt(32)
                m = fmaxf(m, a[ki]);
            } else {
                a[ki] = -INFINITY;
            }
        }
        float sum = 0.f;
        #pragma unroll
        for (int ki = 0; ki < T_CTX; ++ki) {
            a[ki] = __expf(a[ki] - m);   // exp(-inf) = 0 handles mask
            sum += a[ki];
        }
        const float inv = 1.f / sum;
        #pragma unroll
        for (int ki = 0; ki < T_CTX; ++ki)
            sS[h][qi][ki] = a[ki] * inv;
    }
    __syncthreads();

    // ---- stage 3: Y = S @ V per head, concat layout ----
    {
        const int h = c >> 3;
        float y = 0.f;
        #pragma unroll
        for (int ki = 0; ki < T_CTX; ++ki)
            y = fmaf(sS[h][r][ki], sV[ki][c], y);
        sY[r][c] = y;
    }
    __syncthreads();

    // ---- stage 4: Yproj = Ycat @ Wproj.T + bproj ----
    {
        float yp = sB[0][c];
        #pragma unroll
        for (int j = 0; j < DIM; ++j)
            yp = fmaf(sY[r][j], sW[3][c][j], yp);
        sYp[r][c] = yp;
    }
    __syncthreads();

    // ---- stage 5: H1 = relu(Yproj @ W1.T + b1) ----
    {
        float h1 = sB[1][c];
        #pragma unroll
        for (int j = 0; j < DIM; ++j)
            h1 = fmaf(sYp[r][j], sW[4][c][j], h1);
        sH1[r][c] = fmaxf(h1, 0.f);
    }
    __syncthreads();

    // ---- stage 6: Y2 = H1 @ W2.T + b2 ; out = Y2 + Yproj ----
    {
        float y2 = sB[2][c];
        #pragma unroll
        for (int j = 0; j < DIM; ++j)
            y2 = fmaf(sH1[r][j], sW[5][c][j], y2);
        out[tid] = y2 + sYp[r][c];
    }
}

extern "C" void kernel_launch(void* const* d_in, const int* in_sizes, int n_in,
                              void* d_out, int out_size)
{
    const float* X     = (const float*)d_in[0];
    const float* WQ    = (const float*)d_in[1];
    const float* WK    = (const float*)d_in[2];
    const float* WV    = (const float*)d_in[3];
    const float* Wproj = (const float*)d_in[4];
    const float* bproj = (const float*)d_in[5];
    const float* W1    = (const float*)d_in[6];
    const float* b1    = (const float*)d_in[7];
    const float* W2    = (const float*)d_in[8];
    const float* b2    = (const float*)d_in[9];
    float* out = (float*)d_out;

    fused_block_kernel<<<1, NTHREADS>>>(X, WQ, WK, WV, Wproj, bproj,
                                        W1, b1, W2, b2, out);
}

// round 3
// speedup vs baseline: 3.1643x; 1.0048x over previous
#include <cuda_runtime.h>
#include <math.h>

#define T_CTX 5
#define DIM 32
#define HEADS 4
#define HDIM 8
#define NTHREADS (T_CTX * DIM)   // 160
#define WPAD 36                  // padded row stride (floats): 144B, 16B-aligned, conflict-free for LDS.128

__global__ __launch_bounds__(NTHREADS, 1)
void fused_block_kernel(const float* __restrict__ X,
                        const float* __restrict__ WQ,
                        const float* __restrict__ WK,
                        const float* __restrict__ WV,
                        const float* __restrict__ Wproj,
                        const float* __restrict__ bproj,
                        const float* __restrict__ W1,
                        const float* __restrict__ b1,
                        const float* __restrict__ W2,
                        const float* __restrict__ b2,
                        float* __restrict__ out)
{
    // 0:WQ 1:WK 2:WV 3:Wproj 4:W1 5:W2
    __shared__ float sW[6][DIM][WPAD];
    __shared__ float sB[3][DIM];               // bproj, b1, b2
    __shared__ float sX[T_CTX][DIM];
    __shared__ float sQ[T_CTX][DIM];
    __shared__ float sK[T_CTX][DIM];
    __shared__ float sV[T_CTX][DIM];
    __shared__ float sS[HEADS][T_CTX][T_CTX];  // softmax probs
    __shared__ float sY[T_CTX][DIM];           // Ycat
    __shared__ float sYp[T_CTX][DIM];          // Yproj
    __shared__ float sH1[T_CTX][DIM];

    const int tid = threadIdx.x;        // 0..159
    const int r = tid >> 5;             // token row 0..4
    const int c = tid & 31;             // feature col 0..31

    // ---- prefetch: all weights via independent float4 LDGs (max MLP) ----
    #define PREFETCH_W(m, gptr)                                              \
        _Pragma("unroll")                                                    \
        for (int i = tid; i < 256; i += NTHREADS) {                          \
            float4 v = ((const float4*)(gptr))[i];                           \
            *(float4*)&sW[m][i >> 3][(i & 7) << 2] = v;                      \
        }
    PREFETCH_W(0, WQ)
    PREFETCH_W(1, WK)
    PREFETCH_W(2, WV)
    PREFETCH_W(3, Wproj)
    PREFETCH_W(4, W1)
    PREFETCH_W(5, W2)

    if (tid < 3 * DIM) {
        const int which = tid >> 5;     // 0,1,2
        const float* b = (which == 0) ? bproj : (which == 1) ? b1 : b2;
        sB[which][c] = b[c];
    }
    sX[r][c] = X[tid];
    __syncthreads();

    // Helper: vectorized dot of activation row (warp-uniform) with weight row,
    // 4 independent accumulator chains.
    #define DOT32(accname, actrow, wmat)                                     \
        float accname;                                                       \
        {                                                                    \
            const float4* __restrict__ wv = (const float4*)sW[wmat][c];      \
            const float4* __restrict__ xv = (const float4*)(actrow);         \
            float a0 = 0.f, a1 = 0.f, a2 = 0.f, a3 = 0.f;                    \
            _Pragma("unroll")                                                \
            for (int j4 = 0; j4 < 8; ++j4) {                                 \
                const float4 w = wv[j4];                                     \
                const float4 x = xv[j4];                                     \
                a0 = fmaf(x.x, w.x, a0);                                     \
                a1 = fmaf(x.y, w.y, a1);                                     \
                a2 = fmaf(x.z, w.z, a2);                                     \
                a3 = fmaf(x.w, w.w, a3);                                     \
            }                                                                \
            accname = (a0 + a1) + (a2 + a3);                                 \
        }

    // ---- stage 1: Q/K/V projections (x @ W.T) ----
    {
        const float4* __restrict__ xv = (const float4*)sX[r];
        const float4* __restrict__ wq = (const float4*)sW[0][c];
        const float4* __restrict__ wk = (const float4*)sW[1][c];
        const float4* __restrict__ wv4 = (const float4*)sW[2][c];
        float q0 = 0.f, q1 = 0.f, q2 = 0.f, q3 = 0.f;
        float k0 = 0.f, k1 = 0.f, k2 = 0.f, k3 = 0.f;
        float v0 = 0.f, v1 = 0.f, v2 = 0.f, v3 = 0.f;
        #pragma unroll
        for (int j4 = 0; j4 < 8; ++j4) {
            const float4 x = xv[j4];
            const float4 wQ = wq[j4];
            const float4 wK = wk[j4];
            const float4 wV = wv4[j4];
            q0 = fmaf(x.x, wQ.x, q0); q1 = fmaf(x.y, wQ.y, q1);
            q2 = fmaf(x.z, wQ.z, q2); q3 = fmaf(x.w, wQ.w, q3);
            k0 = fmaf(x.x, wK.x, k0); k1 = fmaf(x.y, wK.y, k1);
            k2 = fmaf(x.z, wK.z, k2); k3 = fmaf(x.w, wK.w, k3);
            v0 = fmaf(x.x, wV.x, v0); v1 = fmaf(x.y, wV.y, v1);
            v2 = fmaf(x.z, wV.z, v2); v3 = fmaf(x.w, wV.w, v3);
        }
        sQ[r][c] = (q0 + q1) + (q2 + q3);
        sK[r][c] = (k0 + k1) + (k2 + k3);
        sV[r][c] = (v0 + v1) + (v2 + v3);
    }
    __syncthreads();

    // ---- stage 2: scores + causal mask + softmax, one thread per (h,q) row ----
    if (tid < HEADS * T_CTX) {   // 20 threads
        const int h  = tid / T_CTX;
        const int qi = tid % T_CTX;
        float a[T_CTX];
        float m = -INFINITY;
        #pragma unroll
        for (int ki = 0; ki < T_CTX; ++ki) {
            if (ki <= qi) {
                float s0 = 0.f, s1 = 0.f;
                #pragma unroll
                for (int d = 0; d < HDIM; d += 2) {
                    s0 = fmaf(sQ[qi][h * HDIM + d],     sK[ki][h * HDIM + d],     s0);
                    s1 = fmaf(sQ[qi][h * HDIM + d + 1], sK[ki][h * HDIM + d + 1], s1);
                }
                a[ki] = (s0 + s1) * 0.1767766952966368811f;   // 1/sqrt(32)
                m = fmaxf(m, a[ki]);
            } else {
                a[ki] = -INFINITY;
            }
        }
        float sum = 0.f;
        #pragma unroll
        for (int ki = 0; ki < T_CTX; ++ki) {
            a[ki] = __expf(a[ki] - m);   // exp(-inf) = 0 handles mask
            sum += a[ki];
        }
        const float inv = 1.f / sum;
        #pragma unroll
        for (int ki = 0; ki < T_CTX; ++ki)
            sS[h][qi][ki] = a[ki] * inv;
    }
    __syncthreads();

    // ---- stage 3: Y = S @ V per head, concat layout ----
    {
        const int h = c >> 3;
        float y0 = 0.f, y1 = 0.f;
        y0 = fmaf(sS[h][r][0], sV[0][c], y0);
        y1 = fmaf(sS[h][r][1], sV[1][c], y1);
        y0 = fmaf(sS[h][r][2], sV[2][c], y0);
        y1 = fmaf(sS[h][r][3], sV[3][c], y1);
        y0 = fmaf(sS[h][r][4], sV[4][c], y0);
        sY[r][c] = y0 + y1;
    }
    __syncthreads();

    // ---- stage 4: Yproj = Ycat @ Wproj.T + bproj ----
    {
        DOT32(yp, sY[r], 3)
        sYp[r][c] = yp + sB[0][c];
    }
    __syncthreads();

    // ---- stage 5: H1 = relu(Yproj @ W1.T + b1) ----
    {
        DOT32(h1, sYp[r], 4)
        sH1[r][c] = fmaxf(h1 + sB[1][c], 0.f);
    }
    __syncthreads();

    // ---- stage 6: Y2 = H1 @ W2.T + b2 ; out = Y2 + Yproj ----
    {
        DOT32(y2, sH1[r], 5)
        out[tid] = y2 + sB[2][c] + sYp[r][c];
    }
}

extern "C" void kernel_launch(void* const* d_in, const int* in_sizes, int n_in,
                              void* d_out, int out_size)
{
    const float* X     = (const float*)d_in[0];
    const float* WQ    = (const float*)d_in[1];
    const float* WK    = (const float*)d_in[2];
    const float* WV    = (const float*)d_in[3];
    const float* Wproj = (const float*)d_in[4];
    const float* bproj = (const float*)d_in[5];
    const float* W1    = (const float*)d_in[6];
    const float* b1    = (const float*)d_in[7];
    const float* W2    = (const float*)d_in[8];
    const float* b2    = (const float*)d_in[9];
    float* out = (float*)d_out;

    fused_block_kernel<<<1, NTHREADS>>>(X, WQ, WK, WV, Wproj, bproj,
                                        W1, b1, W2, b2, out);
}